// round 9
// baseline (speedup 1.0000x reference)
#include <cuda_runtime.h>
#include <cuda_fp16.h>
#include <cstdint>
#include <math.h>

#define HID 256
#define NSAMP 64
#define TILE_M 128
#define NTHREADS 512
#define CHB 32768

// ---- global scratch: 16 chunks x 32KB, stream order:
// W2hi c0-3, W2lo c0-3, W3hi c0-3, W3lo c0-3
// chunk layout: [256 rows (N)] x [64 halves (K-slice)] = 128B/row,
// 16B units XOR-swizzled: c' = c ^ (row & 7)
__device__ __align__(128) __half g_imgs[16 * 16384];

// ---------------- helpers ----------------
__device__ __forceinline__ uint32_t smem_u32(const void* p) {
    uint32_t a;
    asm("{ .reg .u64 t; cvta.to.shared.u64 t, %1; cvt.u32.u64 %0, t; }" : "=r"(a) : "l"(p));
    return a;
}
// A tile: [row][256 halves] = 512B/row; 16B chunk permuted: chunk ^= (row & 7)
__device__ __forceinline__ uint32_t tile_off(int row, int col) {
    return (uint32_t)row * 512u + ((((uint32_t)col >> 3) ^ ((uint32_t)row & 7u)) << 4) + ((uint32_t)col & 7u) * 2u;
}
__device__ __forceinline__ void mbar_init(uint32_t a, uint32_t c) {
    asm volatile("mbarrier.init.shared.b64 [%0], %1;" :: "r"(a), "r"(c) : "memory");
}
__device__ __forceinline__ void mbar_expect_tx(uint32_t a, uint32_t b) {
    asm volatile("mbarrier.arrive.expect_tx.shared.b64 _, [%0], %1;" :: "r"(a), "r"(b) : "memory");
}
__device__ __forceinline__ void mbar_arrive(uint32_t a) {
    asm volatile("mbarrier.arrive.shared.b64 _, [%0];" :: "r"(a) : "memory");
}
__device__ __forceinline__ void mbar_wait(uint32_t a, uint32_t ph) {
    asm volatile("{\n\t.reg .pred P;\n\tWL%=:\n\t"
                 "mbarrier.try_wait.parity.acquire.cta.shared::cta.b64 P, [%0], %1, 0x989680;\n\t"
                 "@!P bra WL%=;\n\t}" :: "r"(a), "r"(ph) : "memory");
}
__device__ __forceinline__ void bulk_g2s(uint32_t dst, const void* src, uint32_t bytes, uint32_t mbar) {
    asm volatile("cp.async.bulk.shared::cluster.global.mbarrier::complete_tx::bytes [%0], [%1], %2, [%3];"
                 :: "r"(dst), "l"(src), "r"(bytes), "r"(mbar) : "memory");
}
__device__ __forceinline__ void ldm4(uint32_t* d, uint32_t addr) {
    asm volatile("ldmatrix.sync.aligned.m8n8.x4.shared.b16 {%0,%1,%2,%3}, [%4];"
                 : "=r"(d[0]), "=r"(d[1]), "=r"(d[2]), "=r"(d[3]) : "r"(addr));
}
__device__ __forceinline__ void mma16816(float* c, const uint32_t* a, uint32_t b0, uint32_t b1) {
    asm volatile("mma.sync.aligned.m16n8k16.row.col.f32.f16.f16.f32 "
                 "{%0,%1,%2,%3}, {%4,%5,%6,%7}, {%8,%9}, {%0,%1,%2,%3};"
                 : "+f"(c[0]), "+f"(c[1]), "+f"(c[2]), "+f"(c[3])
                 : "r"(a[0]), "r"(a[1]), "r"(a[2]), "r"(a[3]), "r"(b0), "r"(b1));
}
__device__ __forceinline__ void barg(int id) {    // per-M-group barrier (128 threads)
    asm volatile("bar.sync %0, 128;" :: "r"(id) : "memory");
}
__device__ __forceinline__ float read_scalar(const void* p) {
    uint32_t u = *(const uint32_t*)p;
    if (u >= 0x3F000000u && u < 0x7F800000u) return __uint_as_float(u);
    return (float)(int)u;
}

// ---------------- prep: W (K x N f32) -> hi/lo fp16 chunked swizzled images ----------------
__global__ void __launch_bounds__(256) nerf_prep(const float* __restrict__ W2,
                                                 const float* __restrict__ W3) {
    int idx = blockIdx.x * blockDim.x + threadIdx.x;   // 0 .. 131071
    int m = idx >> 16;       // 0: W2, 1: W3
    int r = idx & 65535;
    int n = r >> 8;          // fan_out -> chunk row
    int k = r & 255;         // fan_in
    const float* W = m ? W3 : W2;
    float v = W[k * HID + n];
    __half hi = __float2half_rn(v);
    __half lo = __float2half_rn(v - __half2float(hi));
    int kc = k >> 6;
    int kl = k & 63;
    int c  = kl >> 3;
    uint32_t off = (uint32_t)n * 64u + (((uint32_t)c ^ ((uint32_t)n & 7u)) << 3) + (uint32_t)(kl & 7);
    g_imgs[(size_t)(m * 8 + kc) * 16384 + off]     = hi;
    g_imgs[(size_t)(m * 8 + 4 + kc) * 16384 + off] = lo;
}

// ---------------- SMEM layout ----------------
// mbars: full0..2 @ 0,8,16 ; empty0..2 @ 24,32,40
#define SM_MB   0
#define SM_AH   1024
#define SM_AL   (1024 + 65536)          // 66560
#define SM_B0   (SM_AL + 65536)         // 132096 ; slots: B0,B1,B2 (32KB each)
#define SMEM_BYTES (SM_B0 + 3 * CHB)    // 230400 < 232448 cap
// W1(768f)+b1(256f) live in the FIRST 4KB of slot B2 (freed before chunk-2 fill).
// red[2048f]+comp[512f] overlay the AL tile (AL dead after chunk 15).

// ---------------- chunk compute (HIH compile-time) ----------------
// MMA order per (ks4, np): 4 independent first-pass MMAs, then 4 correction MMAs.
// RAW distance on every accumulator = 4 MMA issues (covers HMMA latency).
template<bool HIH>
__device__ __forceinline__ void chunk_compute(
    int i, uint32_t sb, int warp, int lane, int cs,
    const uint32_t (&aroffh)[2], const uint32_t (&aroffl)[2], const uint32_t (&asw)[2],
    const uint32_t (&bb)[4], const uint32_t (&bsw)[4],
    float (&cacc)[2][8][4])
{
    const int slot = i % 3;
    const uint32_t sbB  = sb + SM_B0 + (uint32_t)slot * CHB;
    const uint32_t full = sb + SM_MB + slot * 8;
    const uint32_t empt = sb + SM_MB + 24 + slot * 8;
    mbar_wait(full, (i / 3) & 1);
    const int kbase = (i & 3) * 4;
    #pragma unroll
    for (int ks4 = 0; ks4 < 4; ks4++) {
        const uint32_t kk  = (uint32_t)(kbase + ks4) * 2u + (uint32_t)cs;
        const uint32_t kl2 = (uint32_t)ks4 * 2u + (uint32_t)cs;
        // batched fragment loads: A (hi+lo) then first B -> high MLP
        uint32_t af[2][4], al[2][4];
        ldm4(af[0], aroffh[0] + ((kk ^ asw[0]) << 4));
        ldm4(af[1], aroffh[1] + ((kk ^ asw[1]) << 4));
        if (HIH) {
            ldm4(al[0], aroffl[0] + ((kk ^ asw[0]) << 4));
            ldm4(al[1], aroffl[1] + ((kk ^ asw[1]) << 4));
        }
        uint32_t bcur[4], bnxt[4];
        ldm4(bcur, sbB + bb[0] + ((kl2 ^ bsw[0]) << 4));
        #pragma unroll
        for (int np = 0; np < 4; np++) {
            if (np < 3) ldm4(bnxt, sbB + bb[np + 1] + ((kl2 ^ bsw[np + 1]) << 4));
            // first pass: 4 independent MMAs (distinct accumulators)
            mma16816(cacc[0][2 * np],     af[0], bcur[0], bcur[2]);
            mma16816(cacc[1][2 * np],     af[1], bcur[0], bcur[2]);
            mma16816(cacc[0][2 * np + 1], af[0], bcur[1], bcur[3]);
            mma16816(cacc[1][2 * np + 1], af[1], bcur[1], bcur[3]);
            if (HIH) {
                // correction pass: same accumulators, RAW distance = 4 issues
                mma16816(cacc[0][2 * np],     al[0], bcur[0], bcur[2]);
                mma16816(cacc[1][2 * np],     al[1], bcur[0], bcur[2]);
                mma16816(cacc[0][2 * np + 1], al[0], bcur[1], bcur[3]);
                mma16816(cacc[1][2 * np + 1], al[1], bcur[1], bcur[3]);
            }
            if (np < 3) {
                bcur[0] = bnxt[0]; bcur[1] = bnxt[1];
                bcur[2] = bnxt[2]; bcur[3] = bnxt[3];
            }
        }
    }
    if (i + 3 < 16) {
        __syncwarp();
        if (lane == 0) mbar_arrive(empt);          // this warp released slot
        if (warp == slot && lane == 0) {           // round-robin producer (warps 0..2)
            const uint32_t ep = ((uint32_t)(i / 3) + (slot == 2 ? 1u : 0u)) & 1u;
            mbar_wait(empt, ep);                   // all 16 warps released chunk i
            mbar_expect_tx(full, CHB);
            bulk_g2s(sbB, (const char*)g_imgs + (size_t)(i + 3) * CHB, CHB, full);
        }
    }
}

// ---------------- main fused kernel: 1 CTA = 128 points = 2 rays ----------------
__global__ void __launch_bounds__(NTHREADS, 1)
nerf_main(const float* __restrict__ origins, const float* __restrict__ dirs,
          const float* __restrict__ W1, const float* __restrict__ b1,
          const float* __restrict__ b2, const float* __restrict__ b3,
          const float* __restrict__ W4, const float* __restrict__ b4,
          const void* nearp, const void* farp, float* __restrict__ out) {
    extern __shared__ char smem[];
    const uint32_t sb = smem_u32(smem);
    const int tid  = threadIdx.x;
    const int warp = tid >> 5;
    const int lane = tid & 31;
    const int mg   = warp >> 2;          // M-group 0..3
    const int barid = mg + 1;

    float* sW1 = (float*)(smem + SM_B0 + 2 * CHB);   // inside slot B2 (temporary)
    float* sB1 = sW1 + 768;
    float* red  = (float*)(smem + SM_AL);            // overlay on AL (used after chunk 15)
    float* comp = red + 2048;

    // barriers + first two chunk loads (slots 0,1)
    if (tid == 0) {
        #pragma unroll
        for (int s = 0; s < 3; s++) {
            mbar_init(sb + SM_MB + s * 8,      1);   // full_s (tx-based)
            mbar_init(sb + SM_MB + 24 + s * 8, 16);  // empty_s (16 warps)
        }
        mbar_expect_tx(sb + SM_MB + 0, CHB);
        bulk_g2s(sb + SM_B0 + 0 * CHB, (const char*)g_imgs + 0 * CHB, CHB, sb + SM_MB + 0);
        mbar_expect_tx(sb + SM_MB + 8, CHB);
        bulk_g2s(sb + SM_B0 + 1 * CHB, (const char*)g_imgs + 1 * CHB, CHB, sb + SM_MB + 8);
    }

    // stage W1/b1 into B2 slot region
    for (int i = tid; i < 768; i += NTHREADS) sW1[i] = W1[i];
    for (int i = tid; i < 256; i += NTHREADS) sB1[i] = b1[i];
    __syncthreads();     // staging + mbarrier init visible CTA-wide

    // ---- layer 1 (fp32) -> fp16 hi/lo A tiles (rows land inside own M-group) ----
    const float nearv = read_scalar(nearp);
    const float farv  = read_scalar(farp);
    const float delta = (farv - nearv) * (1.0f / NSAMP);
    {
        const int row = tid >> 2;
        const int seg = tid & 3;
        const int p   = blockIdx.x * TILE_M + row;
        const int ray = p >> 6;
        const int s   = p & 63;
        const float z = nearv + (farv - nearv) * ((s + 0.5f) * (1.0f / NSAMP));
        const float px = origins[ray * 3 + 0] + dirs[ray * 3 + 0] * z;
        const float py = origins[ray * 3 + 1] + dirs[ray * 3 + 1] * z;
        const float pz = origins[ray * 3 + 2] + dirs[ray * 3 + 2] * z;
        #pragma unroll
        for (int j0 = seg * 64; j0 < seg * 64 + 64; j0 += 8) {
            uint32_t ph[4], pl[4];
            #pragma unroll
            for (int g = 0; g < 4; g++) {
                int j = j0 + g * 2;
                float h0 = fmaf(px, sW1[j],     fmaf(py, sW1[256 + j],     fmaf(pz, sW1[512 + j],     sB1[j])));
                float h1 = fmaf(px, sW1[j + 1], fmaf(py, sW1[256 + j + 1], fmaf(pz, sW1[512 + j + 1], sB1[j + 1])));
                h0 = fmaxf(h0, 0.0f); h1 = fmaxf(h1, 0.0f);
                __half hh0 = __float2half_rn(h0), hh1 = __float2half_rn(h1);
                __half ll0 = __float2half_rn(h0 - __half2float(hh0));
                __half ll1 = __float2half_rn(h1 - __half2float(hh1));
                __half2 H = __halves2half2(hh0, hh1);
                __half2 L = __halves2half2(ll0, ll1);
                ph[g] = *reinterpret_cast<uint32_t*>(&H);
                pl[g] = *reinterpret_cast<uint32_t*>(&L);
            }
            uint32_t off = tile_off(row, j0);
            *reinterpret_cast<uint4*>(smem + SM_AH + off) = make_uint4(ph[0], ph[1], ph[2], ph[3]);
            *reinterpret_cast<uint4*>(smem + SM_AL + off) = make_uint4(pl[0], pl[1], pl[2], pl[3]);
        }
    }
    // release W1 region (slot B2): completion #0 of empty2 gates the chunk-2 fill
    __syncwarp();
    if (lane == 0) mbar_arrive(sb + SM_MB + 24 + 16);
    if (tid == 0) {
        mbar_wait(sb + SM_MB + 24 + 16, 0);
        mbar_expect_tx(sb + SM_MB + 16, CHB);
        bulk_g2s(sb + SM_B0 + 2 * CHB, (const char*)g_imgs + 2 * (size_t)CHB, CHB, sb + SM_MB + 16);
    }
    barg(barid);        // A-tile rows of this M-group ready

    // ---- warp tiling: 4 M-groups x 4 N-groups ----
    const int m0 = mg * 32;
    const int n0 = (warp & 3) * 64;
    const int quad = lane >> 3;
    const int r8   = lane & 7;
    const int cs   = quad >> 1;
    uint32_t aroffh[2], aroffl[2], asw[2];
    #pragma unroll
    for (int mt = 0; mt < 2; mt++) {
        int ar = m0 + mt * 16 + (quad & 1) * 8 + r8;
        aroffh[mt] = sb + SM_AH + ar * 512;
        aroffl[mt] = sb + SM_AL + ar * 512;
        asw[mt] = ar & 7;
    }
    uint32_t bb[4], bsw[4];
    #pragma unroll
    for (int np = 0; np < 4; np++) {
        int br = n0 + np * 16 + (quad & 1) * 8 + r8;
        bb[np] = (uint32_t)br * 128u;
        bsw[np] = br & 7;
    }

    float cacc[2][8][4];
    #pragma unroll
    for (int mt = 0; mt < 2; mt++)
        #pragma unroll
        for (int nt = 0; nt < 8; nt++)
            #pragma unroll
            for (int q = 0; q < 4; q++) cacc[mt][nt][q] = 0.0f;

    // ---- layer 2: chunks 0-3 (W2 hi, 2 A-passes), 4-7 (W2 lo, 1 A-pass) ----
    #pragma unroll
    for (int i = 0; i < 4; i++)
        chunk_compute<true >(i, sb, warp, lane, cs, aroffh, aroffl, asw, bb, bsw, cacc);
    #pragma unroll
    for (int i = 4; i < 8; i++)
        chunk_compute<false>(i, sb, warp, lane, cs, aroffh, aroffl, asw, bb, bsw, cacc);

    barg(barid);        // all 4 warps of M-group done reading A rows (layer 2)

    // ---- epilogue 1: h2 = relu(C + b2) -> hi/lo fp16 A tiles (b2 from global, L2-hit) ----
    #pragma unroll
    for (int mt = 0; mt < 2; mt++) {
        const int rowa = m0 + mt * 16 + (lane >> 2);
        const int rowb = rowa + 8;
        #pragma unroll
        for (int nt = 0; nt < 8; nt++) {
            const int nc = n0 + nt * 8 + (lane & 3) * 2;
            const float2 bxy = __ldg(reinterpret_cast<const float2*>(&b2[nc]));
            float v0 = fmaxf(cacc[mt][nt][0] + bxy.x, 0.0f);
            float v1 = fmaxf(cacc[mt][nt][1] + bxy.y, 0.0f);
            float v2 = fmaxf(cacc[mt][nt][2] + bxy.x, 0.0f);
            float v3 = fmaxf(cacc[mt][nt][3] + bxy.y, 0.0f);
            __half h0 = __float2half_rn(v0), h1 = __float2half_rn(v1);
            __half h2 = __float2half_rn(v2), h3 = __float2half_rn(v3);
            __half l0 = __float2half_rn(v0 - __half2float(h0));
            __half l1 = __float2half_rn(v1 - __half2float(h1));
            __half l2 = __float2half_rn(v2 - __half2float(h2));
            __half l3 = __float2half_rn(v3 - __half2float(h3));
            __half2 Ha = __halves2half2(h0, h1), Hb = __halves2half2(h2, h3);
            __half2 La = __halves2half2(l0, l1), Lb = __halves2half2(l2, l3);
            uint32_t oa = tile_off(rowa, nc), ob = tile_off(rowb, nc);
            *reinterpret_cast<uint32_t*>(smem + SM_AH + oa) = *reinterpret_cast<uint32_t*>(&Ha);
            *reinterpret_cast<uint32_t*>(smem + SM_AH + ob) = *reinterpret_cast<uint32_t*>(&Hb);
            *reinterpret_cast<uint32_t*>(smem + SM_AL + oa) = *reinterpret_cast<uint32_t*>(&La);
            *reinterpret_cast<uint32_t*>(smem + SM_AL + ob) = *reinterpret_cast<uint32_t*>(&Lb);
            cacc[mt][nt][0] = 0.0f; cacc[mt][nt][1] = 0.0f;
            cacc[mt][nt][2] = 0.0f; cacc[mt][nt][3] = 0.0f;
        }
    }
    barg(barid);        // h2 tile rows of this M-group ready

    // ---- layer 3: chunks 8-11 (W3 hi), 12-15 (W3 lo) ----
    #pragma unroll
    for (int i = 8; i < 12; i++)
        chunk_compute<true >(i, sb, warp, lane, cs, aroffh, aroffl, asw, bb, bsw, cacc);
    #pragma unroll
    for (int i = 12; i < 16; i++)
        chunk_compute<false>(i, sb, warp, lane, cs, aroffh, aroffl, asw, bb, bsw, cacc);

    // ---- layer 4 from registers: h3 = relu(C + b3); o = h3 @ W4 (b3/W4 from global) ----
    float o[2][2][4];
    #pragma unroll
    for (int mt = 0; mt < 2; mt++)
        #pragma unroll
        for (int hh = 0; hh < 2; hh++)
            #pragma unroll
            for (int c = 0; c < 4; c++) o[mt][hh][c] = 0.0f;

    #pragma unroll
    for (int mt = 0; mt < 2; mt++)
        #pragma unroll
        for (int nt = 0; nt < 8; nt++) {
            const int nc = n0 + nt * 8 + (lane & 3) * 2;
            const float2 b3v = __ldg(reinterpret_cast<const float2*>(&b3[nc]));
            const float4 w0 = __ldg(reinterpret_cast<const float4*>(&W4[nc * 4]));
            const float4 w1 = __ldg(reinterpret_cast<const float4*>(&W4[(nc + 1) * 4]));
            #pragma unroll
            for (int hh = 0; hh < 2; hh++) {
                float v0 = fmaxf(cacc[mt][nt][hh * 2]     + b3v.x, 0.0f);
                float v1 = fmaxf(cacc[mt][nt][hh * 2 + 1] + b3v.y, 0.0f);
                o[mt][hh][0] = fmaf(v0, w0.x, fmaf(v1, w1.x, o[mt][hh][0]));
                o[mt][hh][1] = fmaf(v0, w0.y, fmaf(v1, w1.y, o[mt][hh][1]));
                o[mt][hh][2] = fmaf(v0, w0.z, fmaf(v1, w1.z, o[mt][hh][2]));
                o[mt][hh][3] = fmaf(v0, w0.w, fmaf(v1, w1.w, o[mt][hh][3]));
            }
        }
    #pragma unroll
    for (int mt = 0; mt < 2; mt++)
        #pragma unroll
        for (int hh = 0; hh < 2; hh++)
            #pragma unroll
            for (int c = 0; c < 4; c++) {
                float v = o[mt][hh][c];
                v += __shfl_down_sync(0xffffffffu, v, 1, 4);
                v += __shfl_down_sync(0xffffffffu, v, 2, 4);
                o[mt][hh][c] = v;
            }
    if ((lane & 3) == 0) {
        const int ng = warp & 3;
        #pragma unroll
        for (int mt = 0; mt < 2; mt++)
            #pragma unroll
            for (int hh = 0; hh < 2; hh++) {
                const int r = m0 + mt * 16 + (lane >> 2) + hh * 8;
                float* dst = &red[(r * 4 + ng) * 4];
                dst[0] = o[mt][hh][0]; dst[1] = o[mt][hh][1];
                dst[2] = o[mt][hh][2]; dst[3] = o[mt][hh][3];
            }
    }
    __syncthreads();

    // ---- final reduce + activations (one thread per point; b4 from global) ----
    if (tid < TILE_M) {
        float a0 = __ldg(&b4[0]), a1 = __ldg(&b4[1]), a2 = __ldg(&b4[2]), a3 = __ldg(&b4[3]);
        #pragma unroll
        for (int g = 0; g < 4; g++) {
            const float* s = &red[(tid * 4 + g) * 4];
            a0 += s[0]; a1 += s[1]; a2 += s[2]; a3 += s[3];
        }
        float er = 1.0f / (1.0f + expf(-a0));
        float eg = 1.0f / (1.0f + expf(-a1));
        float eb = 1.0f / (1.0f + expf(-a2));
        float alpha = 1.0f - expf(-fmaxf(a3, 0.0f) * delta);
        comp[tid * 4 + 0] = er; comp[tid * 4 + 1] = eg;
        comp[tid * 4 + 2] = eb; comp[tid * 4 + 3] = alpha;
    }
    __syncthreads();

    // ---- alpha compositing: threads 0/1 each own one ray ----
    if (tid < 2) {
        float T = 1.0f, r = 0.0f, g = 0.0f, b = 0.0f;
        #pragma unroll 4
        for (int ss = 0; ss < NSAMP; ss++) {
            const float* c = comp + (tid * NSAMP + ss) * 4;
            float a = c[3];
            float w = a * T;
            r = fmaf(w, c[0], r); g = fmaf(w, c[1], g); b = fmaf(w, c[2], b);
            T *= (1.0f - a + 1e-10f);
        }
        int gray = blockIdx.x * 2 + tid;
        out[gray * 3 + 0] = r; out[gray * 3 + 1] = g; out[gray * 3 + 2] = b;
    }
}

// ---------------- launch ----------------
extern "C" void kernel_launch(void* const* d_in, const int* in_sizes, int n_in,
                              void* d_out, int out_size) {
    const float* origins = (const float*)d_in[0];
    const float* dirs    = (const float*)d_in[1];
    const float* W1      = (const float*)d_in[2];
    const float* b1      = (const float*)d_in[3];
    const float* W2      = (const float*)d_in[4];
    const float* b2      = (const float*)d_in[5];
    const float* W3      = (const float*)d_in[6];
    const float* b3      = (const float*)d_in[7];
    const float* W4      = (const float*)d_in[8];
    const float* b4      = (const float*)d_in[9];
    const void*  nearp   = d_in[10];
    const void*  farp    = d_in[11];
    float* out = (float*)d_out;

    int B = in_sizes[0] / 3;            // 16384 rays
    cudaFuncSetAttribute(nerf_main, cudaFuncAttributeMaxDynamicSharedMemorySize, SMEM_BYTES);

    nerf_prep<<<(2 * HID * HID) / 256, 256>>>(W2, W3);
    nerf_main<<<B / 2, NTHREADS, SMEM_BYTES>>>(origins, dirs, W1, b1, b2, b3, W4, b4, nearp, farp, out);
}

// round 11
// speedup vs baseline: 1.0414x; 1.0414x over previous
#include <cuda_runtime.h>
#include <cuda_fp16.h>
#include <cstdint>
#include <math.h>

#define HID 256
#define NSAMP 64
#define TILE_M 64
#define NTHREADS 256
#define CHB 16384
#define NCHUNK 32

// ---- global scratch: 32 chunks x 16KB, order: W2hi k0-7, W2lo k0-7, W3hi k0-7, W3lo k0-7
// chunk layout: 256 N-rows x 32 K-halves (64B/row), packed 2 N-rows per 128B line:
//   off(n, kl) = (n>>1)*128 + (n&1)*64 + (((kl>>3) ^ ((n>>1)&3))<<4) + (kl&7)*2
__device__ __align__(128) __half g_imgs[NCHUNK * 8192];

// ---------------- helpers ----------------
__device__ __forceinline__ uint32_t smem_u32(const void* p) {
    uint32_t a;
    asm("{ .reg .u64 t; cvta.to.shared.u64 t, %1; cvt.u32.u64 %0, t; }" : "=r"(a) : "l"(p));
    return a;
}
// A tile: [row][256 halves] = 512B/row; 16B units XOR-permuted by (row & 7)
__device__ __forceinline__ uint32_t tile_off(int row, int col) {
    return (uint32_t)row * 512u + ((((uint32_t)col >> 3) ^ ((uint32_t)row & 7u)) << 4) + ((uint32_t)col & 7u) * 2u;
}
__device__ __forceinline__ void mbar_init(uint32_t a, uint32_t c) {
    asm volatile("mbarrier.init.shared.b64 [%0], %1;" :: "r"(a), "r"(c) : "memory");
}
__device__ __forceinline__ void mbar_expect_tx(uint32_t a, uint32_t b) {
    asm volatile("mbarrier.arrive.expect_tx.shared.b64 _, [%0], %1;" :: "r"(a), "r"(b) : "memory");
}
__device__ __forceinline__ void mbar_arrive(uint32_t a) {
    asm volatile("mbarrier.arrive.shared.b64 _, [%0];" :: "r"(a) : "memory");
}
__device__ __forceinline__ void mbar_wait(uint32_t a, uint32_t ph) {
    asm volatile("{\n\t.reg .pred P;\n\tWL%=:\n\t"
                 "mbarrier.try_wait.parity.acquire.cta.shared::cta.b64 P, [%0], %1, 0x989680;\n\t"
                 "@!P bra WL%=;\n\t}" :: "r"(a), "r"(ph) : "memory");
}
__device__ __forceinline__ void bulk_g2s(uint32_t dst, const void* src, uint32_t bytes, uint32_t mbar) {
    asm volatile("cp.async.bulk.shared::cluster.global.mbarrier::complete_tx::bytes [%0], [%1], %2, [%3];"
                 :: "r"(dst), "l"(src), "r"(bytes), "r"(mbar) : "memory");
}
__device__ __forceinline__ void ldm4(uint32_t* d, uint32_t addr) {
    asm volatile("ldmatrix.sync.aligned.m8n8.x4.shared.b16 {%0,%1,%2,%3}, [%4];"
                 : "=r"(d[0]), "=r"(d[1]), "=r"(d[2]), "=r"(d[3]) : "r"(addr));
}
__device__ __forceinline__ void mma16816(float* c, const uint32_t* a, uint32_t b0, uint32_t b1) {
    asm volatile("mma.sync.aligned.m16n8k16.row.col.f32.f16.f16.f32 "
                 "{%0,%1,%2,%3}, {%4,%5,%6,%7}, {%8,%9}, {%0,%1,%2,%3};"
                 : "+f"(c[0]), "+f"(c[1]), "+f"(c[2]), "+f"(c[3])
                 : "r"(a[0]), "r"(a[1]), "r"(a[2]), "r"(a[3]), "r"(b0), "r"(b1));
}
__device__ __forceinline__ float read_scalar(const void* p) {
    uint32_t u = *(const uint32_t*)p;
    if (u >= 0x3F000000u && u < 0x7F800000u) return __uint_as_float(u);
    return (float)(int)u;
}

// ---------------- prep: W (K x N f32) -> hi/lo fp16 chunked swizzled images ----------------
__global__ void __launch_bounds__(256) nerf_prep(const float* __restrict__ W2,
                                                 const float* __restrict__ W3) {
    int idx = blockIdx.x * blockDim.x + threadIdx.x;   // 0 .. 131071
    int m = idx >> 16;       // 0: W2, 1: W3
    int r = idx & 65535;
    int n = r >> 8;          // fan_out (N row)
    int k = r & 255;         // fan_in
    const float* W = m ? W3 : W2;
    float v = W[k * HID + n];
    __half hi = __float2half_rn(v);
    __half lo = __float2half_rn(v - __half2float(hi));
    int kc = k >> 5;         // K-chunk 0..7
    int kl = k & 31;
    uint32_t off = (uint32_t)(n >> 1) * 128u + (uint32_t)(n & 1) * 64u
                 + ((((uint32_t)kl >> 3) ^ (((uint32_t)n >> 1) & 3u)) << 4) + (uint32_t)(kl & 7) * 2u;
    g_imgs[(size_t)(m * 16 + kc)     * 8192 + (off >> 1)] = hi;
    g_imgs[(size_t)(m * 16 + 8 + kc) * 8192 + (off >> 1)] = lo;
}

// ---------------- SMEM layout (per CTA, target 2 CTAs/SM) ----------------
// mbars: full0..2 @ 0,8,16 ; empty0..2 @ 24,32,40
#define SM_MB   0
#define SM_AH   128
#define SM_AL   (128 + 32768)           // 32896
#define SM_B0   (SM_AL + 32768)         // 65664 ; slots B0..B2 (16KB each)
#define SMEM_BYTES (SM_B0 + 3 * CHB)    // 114816 ; x2 CTAs fits 232KB budget
// W1(768f)+b1(256f) staged in first 4KB of slot B2; released by a FULL __syncthreads
// before the chunk-2 fill. red[1024f]+comp[256f] overlay AL, guarded by a FULL
// __syncthreads after the last chunk loop (no reliance on ring skew).

// ---------------- chunk compute (HIH compile-time) ----------------
template<bool HIH>
__device__ __forceinline__ void chunk_compute(
    int i, uint32_t sb, int warp, int lane, int cs,
    const uint32_t (&aroffh)[2], const uint32_t (&aroffl)[2], const uint32_t (&asw)[2],
    const uint32_t (&bb)[4], const uint32_t (&bsw)[4],
    float (&cacc)[2][8][4])
{
    const int slot = i % 3;
    const uint32_t sbB  = sb + SM_B0 + (uint32_t)slot * CHB;
    const uint32_t full = sb + SM_MB + slot * 8;
    const uint32_t empt = sb + SM_MB + 24 + slot * 8;
    mbar_wait(full, (uint32_t)(i / 3) & 1u);
    #pragma unroll
    for (int ks = 0; ks < 2; ks++) {
        const uint32_t kk = (uint32_t)((i & 7) * 2 + ks);          // k16 index 0..15
        const uint32_t au = kk * 2u + (uint32_t)cs;                 // A 16B-unit
        const uint32_t bu = (uint32_t)(ks * 2 + cs);                // B 16B-unit (0..3)
        uint32_t af[2][4], al[2][4];
        ldm4(af[0], aroffh[0] + ((au ^ asw[0]) << 4));
        ldm4(af[1], aroffh[1] + ((au ^ asw[1]) << 4));
        if (HIH) {
            ldm4(al[0], aroffl[0] + ((au ^ asw[0]) << 4));
            ldm4(al[1], aroffl[1] + ((au ^ asw[1]) << 4));
        }
        uint32_t bcur[4], bnxt[4];
        ldm4(bcur, sbB + bb[0] + ((bu ^ bsw[0]) << 4));
        #pragma unroll
        for (int np = 0; np < 4; np++) {
            if (np < 3) ldm4(bnxt, sbB + bb[np + 1] + ((bu ^ bsw[np + 1]) << 4));
            mma16816(cacc[0][2 * np],     af[0], bcur[0], bcur[2]);
            mma16816(cacc[1][2 * np],     af[1], bcur[0], bcur[2]);
            mma16816(cacc[0][2 * np + 1], af[0], bcur[1], bcur[3]);
            mma16816(cacc[1][2 * np + 1], af[1], bcur[1], bcur[3]);
            if (HIH) {
                mma16816(cacc[0][2 * np],     al[0], bcur[0], bcur[2]);
                mma16816(cacc[1][2 * np],     al[1], bcur[0], bcur[2]);
                mma16816(cacc[0][2 * np + 1], al[0], bcur[1], bcur[3]);
                mma16816(cacc[1][2 * np + 1], al[1], bcur[1], bcur[3]);
            }
            if (np < 3) {
                bcur[0] = bnxt[0]; bcur[1] = bnxt[1];
                bcur[2] = bnxt[2]; bcur[3] = bnxt[3];
            }
        }
    }
    if (i + 3 < NCHUNK) {
        __syncwarp();
        if (lane == 0) mbar_arrive(empt);          // this warp released slot
        if (warp == slot && lane == 0) {           // round-robin producer (warps 0..2)
            mbar_wait(empt, (uint32_t)(i / 3) & 1u);  // all 8 warps released chunk i
            mbar_expect_tx(full, CHB);
            bulk_g2s(sbB, (const char*)g_imgs + (size_t)(i + 3) * CHB, CHB, full);
        }
    }
}

// ---------------- main fused kernel: 1 CTA = 64 points = 1 ray ----------------
__global__ void __launch_bounds__(NTHREADS, 2)
nerf_main(const float* __restrict__ origins, const float* __restrict__ dirs,
          const float* __restrict__ W1, const float* __restrict__ b1,
          const float* __restrict__ b2, const float* __restrict__ b3,
          const float* __restrict__ W4, const float* __restrict__ b4,
          const void* nearp, const void* farp, float* __restrict__ out) {
    extern __shared__ char smem[];
    const uint32_t sb = smem_u32(smem);
    const int tid  = threadIdx.x;
    const int warp = tid >> 5;           // 0..7
    const int lane = tid & 31;
    const int mg   = warp >> 2;          // M-group 0..1

    float* sW1 = (float*)(smem + SM_B0 + 2 * CHB);   // inside slot B2 (temporary)
    float* sB1 = sW1 + 768;
    float* red  = (float*)(smem + SM_AL);            // overlay on AL (guarded by syncthreads)
    float* comp = red + 1024;

    // barriers + first two chunk loads (slots 0,1)
    if (tid == 0) {
        #pragma unroll
        for (int s = 0; s < 3; s++) {
            mbar_init(sb + SM_MB + s * 8,      1);   // full_s (tx-based)
            mbar_init(sb + SM_MB + 24 + s * 8, 8);   // empty_s (8 warps)
        }
        mbar_expect_tx(sb + SM_MB + 0, CHB);
        bulk_g2s(sb + SM_B0 + 0 * CHB, (const char*)g_imgs, CHB, sb + SM_MB + 0);
        mbar_expect_tx(sb + SM_MB + 8, CHB);
        bulk_g2s(sb + SM_B0 + 1 * CHB, (const char*)g_imgs + CHB, CHB, sb + SM_MB + 8);
    }

    // stage W1/b1 into slot-B2 region
    for (int i = tid; i < 768; i += NTHREADS) sW1[i] = W1[i];
    for (int i = tid; i < 256; i += NTHREADS) sB1[i] = b1[i];
    __syncthreads();     // staging + mbarrier init visible CTA-wide

    // ---- layer 1 (fp32) -> fp16 hi/lo A tiles ----
    const float nearv = read_scalar(nearp);
    const float farv  = read_scalar(farp);
    const float delta = (farv - nearv) * (1.0f / NSAMP);
    {
        const int row = tid >> 2;        // 0..63 (sample index)
        const int seg = tid & 3;
        const int ray = blockIdx.x;
        const float z = nearv + (farv - nearv) * ((row + 0.5f) * (1.0f / NSAMP));
        const float px = origins[ray * 3 + 0] + dirs[ray * 3 + 0] * z;
        const float py = origins[ray * 3 + 1] + dirs[ray * 3 + 1] * z;
        const float pz = origins[ray * 3 + 2] + dirs[ray * 3 + 2] * z;
        #pragma unroll
        for (int j0 = seg * 64; j0 < seg * 64 + 64; j0 += 8) {
            uint32_t ph[4], pl[4];
            #pragma unroll
            for (int g = 0; g < 4; g++) {
                int j = j0 + g * 2;
                float h0 = fmaf(px, sW1[j],     fmaf(py, sW1[256 + j],     fmaf(pz, sW1[512 + j],     sB1[j])));
                float h1 = fmaf(px, sW1[j + 1], fmaf(py, sW1[256 + j + 1], fmaf(pz, sW1[512 + j + 1], sB1[j + 1])));
                h0 = fmaxf(h0, 0.0f); h1 = fmaxf(h1, 0.0f);
                __half hh0 = __float2half_rn(h0), hh1 = __float2half_rn(h1);
                __half ll0 = __float2half_rn(h0 - __half2float(hh0));
                __half ll1 = __float2half_rn(h1 - __half2float(hh1));
                __half2 H = __halves2half2(hh0, hh1);
                __half2 L = __halves2half2(ll0, ll1);
                ph[g] = *reinterpret_cast<uint32_t*>(&H);
                pl[g] = *reinterpret_cast<uint32_t*>(&L);
            }
            uint32_t off = tile_off(row, j0);
            *reinterpret_cast<uint4*>(smem + SM_AH + off) = make_uint4(ph[0], ph[1], ph[2], ph[3]);
            *reinterpret_cast<uint4*>(smem + SM_AL + off) = make_uint4(pl[0], pl[1], pl[2], pl[3]);
        }
    }
    __syncthreads();     // layer-1 done: A tiles ready, sW1/sB1 reads finished, STS drained
    if (tid == 0) {      // NOW safe to overwrite slot B2 with chunk 2
        mbar_expect_tx(sb + SM_MB + 16, CHB);
        bulk_g2s(sb + SM_B0 + 2 * CHB, (const char*)g_imgs + 2 * (size_t)CHB, CHB, sb + SM_MB + 16);
    }

    // ---- warp tiling: 2 M-groups x 4 N-groups ----
    const int m0 = mg * 32;
    const int n0 = (warp & 3) * 64;
    const int quad = lane >> 3;
    const int r8   = lane & 7;
    const int cs   = quad >> 1;          // k8 select within k16
    uint32_t aroffh[2], aroffl[2], asw[2];
    #pragma unroll
    for (int mt = 0; mt < 2; mt++) {
        int ar = m0 + mt * 16 + (quad & 1) * 8 + r8;
        aroffh[mt] = sb + SM_AH + ar * 512;
        aroffl[mt] = sb + SM_AL + ar * 512;
        asw[mt] = ar & 7;
    }
    uint32_t bb[4], bsw[4];
    #pragma unroll
    for (int np = 0; np < 4; np++) {
        int br = n0 + np * 16 + (quad & 1) * 8 + r8;   // N row 0..255
        bb[np]  = (uint32_t)(br >> 1) * 128u + (uint32_t)(br & 1) * 64u;
        bsw[np] = (uint32_t)(br >> 1) & 3u;
    }

    float cacc[2][8][4];
    #pragma unroll
    for (int mt = 0; mt < 2; mt++)
        #pragma unroll
        for (int nt = 0; nt < 8; nt++)
            #pragma unroll
            for (int q = 0; q < 4; q++) cacc[mt][nt][q] = 0.0f;

    // ---- layer 2: chunks 0-7 (W2 hi, 2 A-passes), 8-15 (W2 lo, 1 A-pass) ----
    #pragma unroll
    for (int i = 0; i < 8; i++)
        chunk_compute<true >(i, sb, warp, lane, cs, aroffh, aroffl, asw, bb, bsw, cacc);
    #pragma unroll
    for (int i = 8; i < 16; i++)
        chunk_compute<false>(i, sb, warp, lane, cs, aroffh, aroffl, asw, bb, bsw, cacc);

    __syncthreads();     // whole CTA done reading A (layer 2)

    // ---- epilogue 1: h2 = relu(C + b2) -> hi/lo fp16 A tiles ----
    #pragma unroll
    for (int mt = 0; mt < 2; mt++) {
        const int rowa = m0 + mt * 16 + (lane >> 2);
        const int rowb = rowa + 8;
        #pragma unroll
        for (int nt = 0; nt < 8; nt++) {
            const int nc = n0 + nt * 8 + (lane & 3) * 2;
            const float2 bxy = __ldg(reinterpret_cast<const float2*>(&b2[nc]));
            float v0 = fmaxf(cacc[mt][nt][0] + bxy.x, 0.0f);
            float v1 = fmaxf(cacc[mt][nt][1] + bxy.y, 0.0f);
            float v2 = fmaxf(cacc[mt][nt][2] + bxy.x, 0.0f);
            float v3 = fmaxf(cacc[mt][nt][3] + bxy.y, 0.0f);
            __half h0 = __float2half_rn(v0), h1 = __float2half_rn(v1);
            __half h2 = __float2half_rn(v2), h3 = __float2half_rn(v3);
            __half l0 = __float2half_rn(v0 - __half2float(h0));
            __half l1 = __float2half_rn(v1 - __half2float(h1));
            __half l2 = __float2half_rn(v2 - __half2float(h2));
            __half l3 = __float2half_rn(v3 - __half2float(h3));
            __half2 Ha = __halves2half2(h0, h1), Hb = __halves2half2(h2, h3);
            __half2 La = __halves2half2(l0, l1), Lb = __halves2half2(l2, l3);
            uint32_t oa = tile_off(rowa, nc), ob = tile_off(rowb, nc);
            *reinterpret_cast<uint32_t*>(smem + SM_AH + oa) = *reinterpret_cast<uint32_t*>(&Ha);
            *reinterpret_cast<uint32_t*>(smem + SM_AH + ob) = *reinterpret_cast<uint32_t*>(&Hb);
            *reinterpret_cast<uint32_t*>(smem + SM_AL + oa) = *reinterpret_cast<uint32_t*>(&La);
            *reinterpret_cast<uint32_t*>(smem + SM_AL + ob) = *reinterpret_cast<uint32_t*>(&Lb);
            cacc[mt][nt][0] = 0.0f; cacc[mt][nt][1] = 0.0f;
            cacc[mt][nt][2] = 0.0f; cacc[mt][nt][3] = 0.0f;
        }
    }
    __syncthreads();     // h2 tiles ready CTA-wide

    // ---- layer 3: chunks 16-23 (W3 hi), 24-31 (W3 lo) ----
    #pragma unroll
    for (int i = 16; i < 24; i++)
        chunk_compute<true >(i, sb, warp, lane, cs, aroffh, aroffl, asw, bb, bsw, cacc);
    #pragma unroll
    for (int i = 24; i < 32; i++)
        chunk_compute<false>(i, sb, warp, lane, cs, aroffh, aroffl, asw, bb, bsw, cacc);

    // ---- layer 4 from registers: h3 = relu(C + b3); o = h3 @ W4 ----
    float o[2][2][4];
    #pragma unroll
    for (int mt = 0; mt < 2; mt++)
        #pragma unroll
        for (int hh = 0; hh < 2; hh++)
            #pragma unroll
            for (int c = 0; c < 4; c++) o[mt][hh][c] = 0.0f;

    #pragma unroll
    for (int mt = 0; mt < 2; mt++)
        #pragma unroll
        for (int nt = 0; nt < 8; nt++) {
            const int nc = n0 + nt * 8 + (lane & 3) * 2;
            const float2 b3v = __ldg(reinterpret_cast<const float2*>(&b3[nc]));
            const float4 w0 = __ldg(reinterpret_cast<const float4*>(&W4[nc * 4]));
            const float4 w1 = __ldg(reinterpret_cast<const float4*>(&W4[(nc + 1) * 4]));
            #pragma unroll
            for (int hh = 0; hh < 2; hh++) {
                float v0 = fmaxf(cacc[mt][nt][hh * 2]     + b3v.x, 0.0f);
                float v1 = fmaxf(cacc[mt][nt][hh * 2 + 1] + b3v.y, 0.0f);
                o[mt][hh][0] = fmaf(v0, w0.x, fmaf(v1, w1.x, o[mt][hh][0]));
                o[mt][hh][1] = fmaf(v0, w0.y, fmaf(v1, w1.y, o[mt][hh][1]));
                o[mt][hh][2] = fmaf(v0, w0.z, fmaf(v1, w1.z, o[mt][hh][2]));
                o[mt][hh][3] = fmaf(v0, w0.w, fmaf(v1, w1.w, o[mt][hh][3]));
            }
        }
    #pragma unroll
    for (int mt = 0; mt < 2; mt++)
        #pragma unroll
        for (int hh = 0; hh < 2; hh++)
            #pragma unroll
            for (int c = 0; c < 4; c++) {
                float v = o[mt][hh][c];
                v += __shfl_down_sync(0xffffffffu, v, 1, 4);
                v += __shfl_down_sync(0xffffffffu, v, 2, 4);
                o[mt][hh][c] = v;
            }

    __syncthreads();     // ALL warps past chunk 31 -> AL region is dead; overlay safe

    if ((lane & 3) == 0) {
        const int ng = warp & 3;
        #pragma unroll
        for (int mt = 0; mt < 2; mt++)
            #pragma unroll
            for (int hh = 0; hh < 2; hh++) {
                const int r = m0 + mt * 16 + (lane >> 2) + hh * 8;   // 0..63
                float* dst = &red[(r * 4 + ng) * 4];
                dst[0] = o[mt][hh][0]; dst[1] = o[mt][hh][1];
                dst[2] = o[mt][hh][2]; dst[3] = o[mt][hh][3];
            }
    }
    __syncthreads();

    // ---- final reduce + activations (one thread per point; b4 from global) ----
    if (tid < TILE_M) {
        float a0 = __ldg(&b4[0]), a1 = __ldg(&b4[1]), a2 = __ldg(&b4[2]), a3 = __ldg(&b4[3]);
        #pragma unroll
        for (int g = 0; g < 4; g++) {
            const float* s = &red[(tid * 4 + g) * 4];
            a0 += s[0]; a1 += s[1]; a2 += s[2]; a3 += s[3];
        }
        float er = 1.0f / (1.0f + expf(-a0));
        float eg = 1.0f / (1.0f + expf(-a1));
        float eb = 1.0f / (1.0f + expf(-a2));
        float alpha = 1.0f - expf(-fmaxf(a3, 0.0f) * delta);
        comp[tid * 4 + 0] = er; comp[tid * 4 + 1] = eg;
        comp[tid * 4 + 2] = eb; comp[tid * 4 + 3] = alpha;
    }
    __syncthreads();

    // ---- alpha compositing: thread 0 owns the ray ----
    if (tid == 0) {
        float T = 1.0f, r = 0.0f, g = 0.0f, b = 0.0f;
        #pragma unroll 4
        for (int ss = 0; ss < NSAMP; ss++) {
            const float* c = comp + ss * 4;
            float a = c[3];
            float w = a * T;
            r = fmaf(w, c[0], r); g = fmaf(w, c[1], g); b = fmaf(w, c[2], b);
            T *= (1.0f - a + 1e-10f);
        }
        out[blockIdx.x * 3 + 0] = r;
        out[blockIdx.x * 3 + 1] = g;
        out[blockIdx.x * 3 + 2] = b;
    }
}

// ---------------- launch ----------------
extern "C" void kernel_launch(void* const* d_in, const int* in_sizes, int n_in,
                              void* d_out, int out_size) {
    const float* origins = (const float*)d_in[0];
    const float* dirs    = (const float*)d_in[1];
    const float* W1      = (const float*)d_in[2];
    const float* b1      = (const float*)d_in[3];
    const float* W2      = (const float*)d_in[4];
    const float* b2      = (const float*)d_in[5];
    const float* W3      = (const float*)d_in[6];
    const float* b3      = (const float*)d_in[7];
    const float* W4      = (const float*)d_in[8];
    const float* b4      = (const float*)d_in[9];
    const void*  nearp   = d_in[10];
    const void*  farp    = d_in[11];
    float* out = (float*)d_out;

    int B = in_sizes[0] / 3;            // 16384 rays -> 1 ray per CTA
    cudaFuncSetAttribute(nerf_main, cudaFuncAttributeMaxDynamicSharedMemorySize, SMEM_BYTES);

    nerf_prep<<<(2 * HID * HID) / 256, 256>>>(W2, W3);
    nerf_main<<<B, NTHREADS, SMEM_BYTES>>>(origins, dirs, W1, b1, b2, b3, W4, b4, nearp, farp, out);
}

// round 13
// speedup vs baseline: 1.0436x; 1.0021x over previous
#include <cuda_runtime.h>
#include <cuda_fp16.h>
#include <cstdint>
#include <math.h>

#define HID 256
#define NSAMP 64
#define TILE_M 64
#define NTHREADS 256
#define CHB 16384
#define NCHUNK 32

// ---- global scratch: 32 chunks x 16KB, order: W2hi k0-7, W2lo k0-7, W3hi k0-7, W3lo k0-7
// chunk layout: 256 N-rows x 32 K-halves (64B/row), packed 2 N-rows per 128B line:
//   off(n, kl) = (n>>1)*128 + (n&1)*64 + (((kl>>3) ^ ((n>>1)&3))<<4) + (kl&7)*2
__device__ __align__(128) __half g_imgs[NCHUNK * 8192];

// ---------------- helpers ----------------
__device__ __forceinline__ uint32_t smem_u32(const void* p) {
    uint32_t a;
    asm("{ .reg .u64 t; cvta.to.shared.u64 t, %1; cvt.u32.u64 %0, t; }" : "=r"(a) : "l"(p));
    return a;
}
// A tile: [row][256 halves] = 512B/row; 16B units XOR-permuted by (row & 7)
__device__ __forceinline__ uint32_t tile_off(int row, int col) {
    return (uint32_t)row * 512u + ((((uint32_t)col >> 3) ^ ((uint32_t)row & 7u)) << 4) + ((uint32_t)col & 7u) * 2u;
}
__device__ __forceinline__ void mbar_init(uint32_t a, uint32_t c) {
    asm volatile("mbarrier.init.shared.b64 [%0], %1;" :: "r"(a), "r"(c) : "memory");
}
__device__ __forceinline__ void mbar_expect_tx(uint32_t a, uint32_t b) {
    asm volatile("mbarrier.arrive.expect_tx.shared.b64 _, [%0], %1;" :: "r"(a), "r"(b) : "memory");
}
__device__ __forceinline__ void mbar_arrive(uint32_t a) {
    asm volatile("mbarrier.arrive.shared.b64 _, [%0];" :: "r"(a) : "memory");
}
__device__ __forceinline__ void mbar_wait(uint32_t a, uint32_t ph) {
    asm volatile("{\n\t.reg .pred P;\n\tWL%=:\n\t"
                 "mbarrier.try_wait.parity.acquire.cta.shared::cta.b64 P, [%0], %1, 0x989680;\n\t"
                 "@!P bra WL%=;\n\t}" :: "r"(a), "r"(ph) : "memory");
}
__device__ __forceinline__ void bulk_g2s(uint32_t dst, const void* src, uint32_t bytes, uint32_t mbar) {
    asm volatile("cp.async.bulk.shared::cluster.global.mbarrier::complete_tx::bytes [%0], [%1], %2, [%3];"
                 :: "r"(dst), "l"(src), "r"(bytes), "r"(mbar) : "memory");
}
__device__ __forceinline__ void ldm4(uint32_t* d, uint32_t addr) {
    asm volatile("ldmatrix.sync.aligned.m8n8.x4.shared.b16 {%0,%1,%2,%3}, [%4];"
                 : "=r"(d[0]), "=r"(d[1]), "=r"(d[2]), "=r"(d[3]) : "r"(addr));
}
__device__ __forceinline__ void mma16816(float* c, const uint32_t* a, uint32_t b0, uint32_t b1) {
    asm volatile("mma.sync.aligned.m16n8k16.row.col.f32.f16.f16.f32 "
                 "{%0,%1,%2,%3}, {%4,%5,%6,%7}, {%8,%9}, {%0,%1,%2,%3};"
                 : "+f"(c[0]), "+f"(c[1]), "+f"(c[2]), "+f"(c[3])
                 : "r"(a[0]), "r"(a[1]), "r"(a[2]), "r"(a[3]), "r"(b0), "r"(b1));
}
__device__ __forceinline__ float read_scalar(const void* p) {
    uint32_t u = *(const uint32_t*)p;
    if (u >= 0x3F000000u && u < 0x7F800000u) return __uint_as_float(u);
    return (float)(int)u;
}

// ---------------- prep: W (K x N f32) -> hi/lo fp16 chunked swizzled images ----------------
__global__ void __launch_bounds__(256) nerf_prep(const float* __restrict__ W2,
                                                 const float* __restrict__ W3) {
    int idx = blockIdx.x * blockDim.x + threadIdx.x;   // 0 .. 131071
    int m = idx >> 16;       // 0: W2, 1: W3
    int r = idx & 65535;
    int n = r >> 8;          // fan_out (N row)
    int k = r & 255;         // fan_in
    const float* W = m ? W3 : W2;
    float v = W[k * HID + n];
    __half hi = __float2half_rn(v);
    __half lo = __float2half_rn(v - __half2float(hi));
    int kc = k >> 5;         // K-chunk 0..7
    int kl = k & 31;
    uint32_t off = (uint32_t)(n >> 1) * 128u + (uint32_t)(n & 1) * 64u
                 + ((((uint32_t)kl >> 3) ^ (((uint32_t)n >> 1) & 3u)) << 4) + (uint32_t)(kl & 7) * 2u;
    g_imgs[(size_t)(m * 16 + kc)     * 8192 + (off >> 1)] = hi;
    g_imgs[(size_t)(m * 16 + 8 + kc) * 8192 + (off >> 1)] = lo;
}

// ---------------- SMEM layout (per CTA, 2 CTAs/SM) ----------------
// mbars: full0..2 @ 0,8,16 ; empty0..2 @ 24,32,40
#define SM_MB   0
#define SM_AH   128
#define SM_AL   (128 + 32768)           // 32896
#define SM_B0   (SM_AL + 32768)         // 65664 ; slots B0..B2 (16KB each)
#define SMEM_BYTES (SM_B0 + 3 * CHB)    // 114816 ; x2 CTAs fits 232KB budget
// W1(768f)+b1(256f) staged in first 4KB of slot B2; released by a FULL __syncthreads
// before the chunk-2 fill. red[1024f]+comp[256f] overlay AL, guarded by __syncthreads.

// ---------------- chunk compute (HIH compile-time) ----------------
// Early slot release: each warp arrives on the empty barrier right after its LAST
// ldmatrix of the chunk (start of the ks==1, np==3 iteration) — ldmatrix is
// warp-collective and convergent, so all lanes' slot reads are complete there.
template<bool HIH>
__device__ __forceinline__ void chunk_compute(
    int i, uint32_t sb, int warp, int lane, int cs,
    const uint32_t (&aroffh)[2], const uint32_t (&aroffl)[2], const uint32_t (&asw)[2],
    const uint32_t (&bb)[4], const uint32_t (&bsw)[4],
    float (&cacc)[2][8][4])
{
    const int slot = i % 3;
    const uint32_t sbB  = sb + SM_B0 + (uint32_t)slot * CHB;
    const uint32_t full = sb + SM_MB + slot * 8;
    const uint32_t empt = sb + SM_MB + 24 + slot * 8;
    mbar_wait(full, (uint32_t)(i / 3) & 1u);
    #pragma unroll
    for (int ks = 0; ks < 2; ks++) {
        const uint32_t kk = (uint32_t)((i & 7) * 2 + ks);          // k16 index 0..15
        const uint32_t au = kk * 2u + (uint32_t)cs;                 // A 16B-unit
        const uint32_t bu = (uint32_t)(ks * 2 + cs);                // B 16B-unit (0..3)
        uint32_t af[2][4], al[2][4];
        ldm4(af[0], aroffh[0] + ((au ^ asw[0]) << 4));
        ldm4(af[1], aroffh[1] + ((au ^ asw[1]) << 4));
        if (HIH) {
            ldm4(al[0], aroffl[0] + ((au ^ asw[0]) << 4));
            ldm4(al[1], aroffl[1] + ((au ^ asw[1]) << 4));
        }
        uint32_t bcur[4], bnxt[4];
        ldm4(bcur, sbB + bb[0] + ((bu ^ bsw[0]) << 4));
        #pragma unroll
        for (int np = 0; np < 4; np++) {
            if (np < 3) ldm4(bnxt, sbB + bb[np + 1] + ((bu ^ bsw[np + 1]) << 4));
            // Early release: all ldm4s of this chunk are done at (ks==1, np==3).
            if (ks == 1 && np == 3 && i + 3 < NCHUNK && lane == 0)
                mbar_arrive(empt);
            mma16816(cacc[0][2 * np],     af[0], bcur[0], bcur[2]);
            mma16816(cacc[1][2 * np],     af[1], bcur[0], bcur[2]);
            mma16816(cacc[0][2 * np + 1], af[0], bcur[1], bcur[3]);
            mma16816(cacc[1][2 * np + 1], af[1], bcur[1], bcur[3]);
            if (HIH) {
                mma16816(cacc[0][2 * np],     al[0], bcur[0], bcur[2]);
                mma16816(cacc[1][2 * np],     al[1], bcur[0], bcur[2]);
                mma16816(cacc[0][2 * np + 1], al[0], bcur[1], bcur[3]);
                mma16816(cacc[1][2 * np + 1], al[1], bcur[1], bcur[3]);
            }
            if (np < 3) {
                bcur[0] = bnxt[0]; bcur[1] = bnxt[1];
                bcur[2] = bnxt[2]; bcur[3] = bnxt[3];
            }
        }
    }
    if (i + 3 < NCHUNK) {
        if (warp == slot && lane == 0) {           // round-robin producer (warps 0..2)
            mbar_wait(empt, (uint32_t)(i / 3) & 1u);  // all 8 warps released chunk i
            mbar_expect_tx(full, CHB);
            bulk_g2s(sbB, (const char*)g_imgs + (size_t)(i + 3) * CHB, CHB, full);
        }
    }
}

// ---------------- main fused kernel: 1 CTA = 64 points = 1 ray ----------------
__global__ void __launch_bounds__(NTHREADS, 2)
nerf_main(const float* __restrict__ origins, const float* __restrict__ dirs,
          const float* __restrict__ W1, const float* __restrict__ b1,
          const float* __restrict__ b2, const float* __restrict__ b3,
          const float* __restrict__ W4, const float* __restrict__ b4,
          const void* nearp, const void* farp, float* __restrict__ out) {
    extern __shared__ char smem[];
    const uint32_t sb = smem_u32(smem);
    const int tid  = threadIdx.x;
    const int warp = tid >> 5;           // 0..7
    const int lane = tid & 31;
    const int mg   = warp >> 2;          // M-group 0..1

    float* sW1 = (float*)(smem + SM_B0 + 2 * CHB);   // inside slot B2 (temporary)
    float* sB1 = sW1 + 768;
    float* red  = (float*)(smem + SM_AL);            // overlay on AL (guarded by syncthreads)
    float* comp = red + 1024;

    // barriers + first two chunk loads (slots 0,1)
    if (tid == 0) {
        #pragma unroll
        for (int s = 0; s < 3; s++) {
            mbar_init(sb + SM_MB + s * 8,      1);   // full_s (tx-based)
            mbar_init(sb + SM_MB + 24 + s * 8, 8);   // empty_s (8 warps)
        }
        mbar_expect_tx(sb + SM_MB + 0, CHB);
        bulk_g2s(sb + SM_B0 + 0 * CHB, (const char*)g_imgs, CHB, sb + SM_MB + 0);
        mbar_expect_tx(sb + SM_MB + 8, CHB);
        bulk_g2s(sb + SM_B0 + 1 * CHB, (const char*)g_imgs + CHB, CHB, sb + SM_MB + 8);
    }

    // stage W1/b1 into slot-B2 region
    for (int i = tid; i < 768; i += NTHREADS) sW1[i] = W1[i];
    for (int i = tid; i < 256; i += NTHREADS) sB1[i] = b1[i];
    __syncthreads();     // staging + mbarrier init visible CTA-wide

    // ---- layer 1 (fp32) -> fp16 hi/lo A tiles ----
    const float nearv = read_scalar(nearp);
    const float farv  = read_scalar(farp);
    const float delta = (farv - nearv) * (1.0f / NSAMP);
    {
        const int row = tid >> 2;        // 0..63 (sample index)
        const int seg = tid & 3;
        const int ray = blockIdx.x;
        const float z = nearv + (farv - nearv) * ((row + 0.5f) * (1.0f / NSAMP));
        const float px = origins[ray * 3 + 0] + dirs[ray * 3 + 0] * z;
        const float py = origins[ray * 3 + 1] + dirs[ray * 3 + 1] * z;
        const float pz = origins[ray * 3 + 2] + dirs[ray * 3 + 2] * z;
        #pragma unroll
        for (int j0 = seg * 64; j0 < seg * 64 + 64; j0 += 8) {
            uint32_t ph[4], pl[4];
            #pragma unroll
            for (int g = 0; g < 4; g++) {
                int j = j0 + g * 2;
                float h0 = fmaf(px, sW1[j],     fmaf(py, sW1[256 + j],     fmaf(pz, sW1[512 + j],     sB1[j])));
                float h1 = fmaf(px, sW1[j + 1], fmaf(py, sW1[256 + j + 1], fmaf(pz, sW1[512 + j + 1], sB1[j + 1])));
                h0 = fmaxf(h0, 0.0f); h1 = fmaxf(h1, 0.0f);
                __half hh0 = __float2half_rn(h0), hh1 = __float2half_rn(h1);
                __half ll0 = __float2half_rn(h0 - __half2float(hh0));
                __half ll1 = __float2half_rn(h1 - __half2float(hh1));
                __half2 H = __halves2half2(hh0, hh1);
                __half2 L = __halves2half2(ll0, ll1);
                ph[g] = *reinterpret_cast<uint32_t*>(&H);
                pl[g] = *reinterpret_cast<uint32_t*>(&L);
            }
            uint32_t off = tile_off(row, j0);
            *reinterpret_cast<uint4*>(smem + SM_AH + off) = make_uint4(ph[0], ph[1], ph[2], ph[3]);
            *reinterpret_cast<uint4*>(smem + SM_AL + off) = make_uint4(pl[0], pl[1], pl[2], pl[3]);
        }
    }
    __syncthreads();     // layer-1 done: A tiles ready, sW1/sB1 reads finished, STS drained
    if (tid == 0) {      // NOW safe to overwrite slot B2 with chunk 2
        mbar_expect_tx(sb + SM_MB + 16, CHB);
        bulk_g2s(sb + SM_B0 + 2 * CHB, (const char*)g_imgs + 2 * (size_t)CHB, CHB, sb + SM_MB + 16);
    }

    // ---- warp tiling: 2 M-groups x 4 N-groups ----
    const int m0 = mg * 32;
    const int n0 = (warp & 3) * 64;
    const int quad = lane >> 3;
    const int r8   = lane & 7;
    const int cs   = quad >> 1;          // k8 select within k16
    uint32_t aroffh[2], aroffl[2], asw[2];
    #pragma unroll
    for (int mt = 0; mt < 2; mt++) {
        int ar = m0 + mt * 16 + (quad & 1) * 8 + r8;
        aroffh[mt] = sb + SM_AH + ar * 512;
        aroffl[mt] = sb + SM_AL + ar * 512;
        asw[mt] = ar & 7;
    }
    uint32_t bb[4], bsw[4];
    #pragma unroll
    for (int np = 0; np < 4; np++) {
        int br = n0 + np * 16 + (quad & 1) * 8 + r8;   // N row 0..255
        bb[np]  = (uint32_t)(br >> 1) * 128u + (uint32_t)(br & 1) * 64u;
        bsw[np] = (uint32_t)(br >> 1) & 3u;
    }

    float cacc[2][8][4];
    #pragma unroll
    for (int mt = 0; mt < 2; mt++)
        #pragma unroll
        for (int nt = 0; nt < 8; nt++)
            #pragma unroll
            for (int q = 0; q < 4; q++) cacc[mt][nt][q] = 0.0f;

    // ---- layer 2: chunks 0-7 (W2 hi, 2 A-passes), 8-15 (W2 lo, 1 A-pass) ----
    #pragma unroll
    for (int i = 0; i < 8; i++)
        chunk_compute<true >(i, sb, warp, lane, cs, aroffh, aroffl, asw, bb, bsw, cacc);
    #pragma unroll
    for (int i = 8; i < 16; i++)
        chunk_compute<false>(i, sb, warp, lane, cs, aroffh, aroffl, asw, bb, bsw, cacc);

    __syncthreads();     // whole CTA done reading A (layer 2)

    // ---- epilogue 1: h2 = relu(C + b2) -> hi/lo fp16 A tiles ----
    #pragma unroll
    for (int mt = 0; mt < 2; mt++) {
        const int rowa = m0 + mt * 16 + (lane >> 2);
        const int rowb = rowa + 8;
        #pragma unroll
        for (int nt = 0; nt < 8; nt++) {
            const int nc = n0 + nt * 8 + (lane & 3) * 2;
            const float2 bxy = __ldg(reinterpret_cast<const float2*>(&b2[nc]));
            float v0 = fmaxf(cacc[mt][nt][0] + bxy.x, 0.0f);
            float v1 = fmaxf(cacc[mt][nt][1] + bxy.y, 0.0f);
            float v2 = fmaxf(cacc[mt][nt][2] + bxy.x, 0.0f);
            float v3 = fmaxf(cacc[mt][nt][3] + bxy.y, 0.0f);
            __half h0 = __float2half_rn(v0), h1 = __float2half_rn(v1);
            __half h2 = __float2half_rn(v2), h3 = __float2half_rn(v3);
            __half l0 = __float2half_rn(v0 - __half2float(h0));
            __half l1 = __float2half_rn(v1 - __half2float(h1));
            __half l2 = __float2half_rn(v2 - __half2float(h2));
            __half l3 = __float2half_rn(v3 - __half2float(h3));
            __half2 Ha = __halves2half2(h0, h1), Hb = __halves2half2(h2, h3);
            __half2 La = __halves2half2(l0, l1), Lb = __halves2half2(l2, l3);
            uint32_t oa = tile_off(rowa, nc), ob = tile_off(rowb, nc);
            *reinterpret_cast<uint32_t*>(smem + SM_AH + oa) = *reinterpret_cast<uint32_t*>(&Ha);
            *reinterpret_cast<uint32_t*>(smem + SM_AH + ob) = *reinterpret_cast<uint32_t*>(&Hb);
            *reinterpret_cast<uint32_t*>(smem + SM_AL + oa) = *reinterpret_cast<uint32_t*>(&La);
            *reinterpret_cast<uint32_t*>(smem + SM_AL + ob) = *reinterpret_cast<uint32_t*>(&Lb);
            cacc[mt][nt][0] = 0.0f; cacc[mt][nt][1] = 0.0f;
            cacc[mt][nt][2] = 0.0f; cacc[mt][nt][3] = 0.0f;
        }
    }
    __syncthreads();     // h2 tiles ready CTA-wide

    // ---- layer 3: chunks 16-23 (W3 hi), 24-31 (W3 lo) ----
    #pragma unroll
    for (int i = 16; i < 24; i++)
        chunk_compute<true >(i, sb, warp, lane, cs, aroffh, aroffl, asw, bb, bsw, cacc);
    #pragma unroll
    for (int i = 24; i < 32; i++)
        chunk_compute<false>(i, sb, warp, lane, cs, aroffh, aroffl, asw, bb, bsw, cacc);

    // ---- layer 4 from registers: h3 = relu(C + b3); o = h3 @ W4 ----
    float o[2][2][4];
    #pragma unroll
    for (int mt = 0; mt < 2; mt++)
        #pragma unroll
        for (int hh = 0; hh < 2; hh++)
            #pragma unroll
            for (int c = 0; c < 4; c++) o[mt][hh][c] = 0.0f;

    #pragma unroll
    for (int mt = 0; mt < 2; mt++)
        #pragma unroll
        for (int nt = 0; nt < 8; nt++) {
            const int nc = n0 + nt * 8 + (lane & 3) * 2;
            const float2 b3v = __ldg(reinterpret_cast<const float2*>(&b3[nc]));
            const float4 w0 = __ldg(reinterpret_cast<const float4*>(&W4[nc * 4]));
            const float4 w1 = __ldg(reinterpret_cast<const float4*>(&W4[(nc + 1) * 4]));
            #pragma unroll
            for (int hh = 0; hh < 2; hh++) {
                float v0 = fmaxf(cacc[mt][nt][hh * 2]     + b3v.x, 0.0f);
                float v1 = fmaxf(cacc[mt][nt][hh * 2 + 1] + b3v.y, 0.0f);
                o[mt][hh][0] = fmaf(v0, w0.x, fmaf(v1, w1.x, o[mt][hh][0]));
                o[mt][hh][1] = fmaf(v0, w0.y, fmaf(v1, w1.y, o[mt][hh][1]));
                o[mt][hh][2] = fmaf(v0, w0.z, fmaf(v1, w1.z, o[mt][hh][2]));
                o[mt][hh][3] = fmaf(v0, w0.w, fmaf(v1, w1.w, o[mt][hh][3]));
            }
        }
    #pragma unroll
    for (int mt = 0; mt < 2; mt++)
        #pragma unroll
        for (int hh = 0; hh < 2; hh++)
            #pragma unroll
            for (int c = 0; c < 4; c++) {
                float v = o[mt][hh][c];
                v += __shfl_down_sync(0xffffffffu, v, 1, 4);
                v += __shfl_down_sync(0xffffffffu, v, 2, 4);
                o[mt][hh][c] = v;
            }

    __syncthreads();     // ALL warps past chunk 31 -> AL region is dead; overlay safe

    if ((lane & 3) == 0) {
        const int ng = warp & 3;
        #pragma unroll
        for (int mt = 0; mt < 2; mt++)
            #pragma unroll
            for (int hh = 0; hh < 2; hh++) {
                const int r = m0 + mt * 16 + (lane >> 2) + hh * 8;   // 0..63
                float* dst = &red[(r * 4 + ng) * 4];
                dst[0] = o[mt][hh][0]; dst[1] = o[mt][hh][1];
                dst[2] = o[mt][hh][2]; dst[3] = o[mt][hh][3];
            }
    }
    __syncthreads();

    // ---- final reduce + activations (one thread per point; b4 from global) ----
    if (tid < TILE_M) {
        float a0 = __ldg(&b4[0]), a1 = __ldg(&b4[1]), a2 = __ldg(&b4[2]), a3 = __ldg(&b4[3]);
        #pragma unroll
        for (int g = 0; g < 4; g++) {
            const float* s = &red[(tid * 4 + g) * 4];
            a0 += s[0]; a1 += s[1]; a2 += s[2]; a3 += s[3];
        }
        float er = 1.0f / (1.0f + expf(-a0));
        float eg = 1.0f / (1.0f + expf(-a1));
        float eb = 1.0f / (1.0f + expf(-a2));
        float alpha = 1.0f - expf(-fmaxf(a3, 0.0f) * delta);
        comp[tid * 4 + 0] = er; comp[tid * 4 + 1] = eg;
        comp[tid * 4 + 2] = eb; comp[tid * 4 + 3] = alpha;
    }
    __syncthreads();

    // ---- alpha compositing: thread 0 owns the ray ----
    if (tid == 0) {
        float T = 1.0f, r = 0.0f, g = 0.0f, b = 0.0f;
        #pragma unroll 4
        for (int ss = 0; ss < NSAMP; ss++) {
            const float* c = comp + ss * 4;
            float a = c[3];
            float w = a * T;
            r = fmaf(w, c[0], r); g = fmaf(w, c[1], g); b = fmaf(w, c[2], b);
            T *= (1.0f - a + 1e-10f);
        }
        out[blockIdx.x * 3 + 0] = r;
        out[blockIdx.x * 3 + 1] = g;
        out[blockIdx.x * 3 + 2] = b;
    }
}

// ---------------- launch ----------------
extern "C" void kernel_launch(void* const* d_in, const int* in_sizes, int n_in,
                              void* d_out, int out_size) {
    const float* origins = (const float*)d_in[0];
    const float* dirs    = (const float*)d_in[1];
    const float* W1      = (const float*)d_in[2];
    const float* b1      = (const float*)d_in[3];
    const float* W2      = (const float*)d_in[4];
    const float* b2      = (const float*)d_in[5];
    const float* W3      = (const float*)d_in[6];
    const float* b3      = (const float*)d_in[7];
    const float* W4      = (const float*)d_in[8];
    const float* b4      = (const float*)d_in[9];
    const void*  nearp   = d_in[10];
    const void*  farp    = d_in[11];
    float* out = (float*)d_out;

    int B = in_sizes[0] / 3;            // 16384 rays -> 1 ray per CTA
    cudaFuncSetAttribute(nerf_main, cudaFuncAttributeMaxDynamicSharedMemorySize, SMEM_BYTES);

    nerf_prep<<<(2 * HID * HID) / 256, 256>>>(W2, W3);
    nerf_main<<<B, NTHREADS, SMEM_BYTES>>>(origins, dirs, W1, b1, b2, b3, W4, b4, nearp, farp, out);
}